// round 1
// baseline (speedup 1.0000x reference)
#include <cuda_runtime.h>

#define BB 64
#define TT 512
#define DD 768
#define NSPLIT 4
#define TCHUNK (TT / NSPLIT)

// scratch (no allocations allowed)
__device__ float g_w[2 * BB * TT];        // per-(stream,b,t) weights
__device__ float g_ne[2 * BB];            // nonempty flags
__device__ float g_part[2 * BB * NSPLIT * DD]; // partial sums

// log2(0.9)
#define LOG2_DECAY (-0.15200309344504995f)

__global__ void weight_kernel(const float* __restrict__ spk_mask,
                              const float* __restrict__ act_mask) {
    int b = blockIdx.x;
    int s = blockIdx.y;
    int t = threadIdx.x;
    const float* mask = (s == 0) ? spk_mask : act_mask;
    float mf = mask[b * TT + t];
    int m = (mf > 0.5f) ? 1 : 0;

    __shared__ int sc[TT];
    sc[t] = m;
    __syncthreads();
    // Hillis-Steele inclusive scan over 512 elements
    #pragma unroll
    for (int off = 1; off < TT; off <<= 1) {
        int v = (t >= off) ? sc[t - off] : 0;
        __syncthreads();
        sc[t] += v;
        __syncthreads();
    }
    int C = sc[TT - 1];
    int k = C - sc[t];  // masked steps strictly after t
    float w = m ? 0.1f * exp2f((float)k * LOG2_DECAY) : 0.0f;
    if (w < 1e-12f) w = 0.0f;  // numerically irrelevant -> allows load skipping
    g_w[(s * BB + b) * TT + t] = w;
    if (t == 0) g_ne[s * BB + b] = (C > 0) ? 1.0f : 0.0f;
}

__global__ void __launch_bounds__(192) sum_kernel(const float* __restrict__ spk,
                                                  const float* __restrict__ act) {
    int b = blockIdx.x;
    int s = blockIdx.y;
    int z = blockIdx.z;
    const float* X = (s == 0) ? spk : act;
    int tid = threadIdx.x;  // one float4 column of D (192 * 4 = 768)

    __shared__ float sw[TCHUNK];
    if (tid < TCHUNK) sw[tid] = g_w[(s * BB + b) * TT + z * TCHUNK + tid];
    __syncthreads();

    const float4* Xp =
        (const float4*)(X + ((size_t)b * TT + (size_t)z * TCHUNK) * DD) + tid;
    float4 acc = make_float4(0.f, 0.f, 0.f, 0.f);

    #pragma unroll 4
    for (int i = 0; i < TCHUNK; i++) {
        float w = sw[i];
        if (w != 0.0f) {  // block-uniform branch: skip whole t-rows
            float4 v = Xp[(size_t)i * (DD / 4)];
            acc.x += w * v.x;
            acc.y += w * v.y;
            acc.z += w * v.z;
            acc.w += w * v.w;
        }
    }
    ((float4*)g_part)[((s * BB + b) * NSPLIT + z) * (DD / 4) + tid] = acc;
}

__global__ void __launch_bounds__(DD) final_kernel(const float* __restrict__ spk_mean,
                                                   const float* __restrict__ act_mean,
                                                   const float* __restrict__ mix_logits,
                                                   float* __restrict__ out) {
    int b = blockIdx.x;
    int d = threadIdx.x;

    float l0 = mix_logits[0], l1 = mix_logits[1];
    float mx = fmaxf(l0, l1);
    float e0 = expf(l0 - mx), e1 = expf(l1 - mx);
    float inv = 1.0f / (e0 + e1);
    float w0 = e0 * inv, w1 = e1 * inv;

    const float* p0 = &g_part[(0 * BB + b) * NSPLIT * DD + d];
    float sum0 = p0[0] + p0[DD] + p0[2 * DD] + p0[3 * DD];
    float cs = (g_ne[b] > 0.f) ? sum0 : spk_mean[b * DD + d];

    const float* p1 = &g_part[(1 * BB + b) * NSPLIT * DD + d];
    float sum1 = p1[0] + p1[DD] + p1[2 * DD] + p1[3 * DD];
    float ca = (g_ne[BB + b] > 0.f) ? sum1 : act_mean[b * DD + d];

    out[b * DD + d] = w0 * cs + w1 * ca;                 // c
    out[BB * DD + b * DD + d] = cs;                      // c_spk
    out[2 * BB * DD + b * DD + d] = ca;                  // c_act
    if (b == 0 && d < 2) out[3 * BB * DD + d] = (d == 0) ? w0 : w1;  // w
}

extern "C" void kernel_launch(void* const* d_in, const int* in_sizes, int n_in,
                              void* d_out, int out_size) {
    const float* spk_hist = (const float*)d_in[0];
    const float* spk_mask = (const float*)d_in[1];
    const float* act_hist = (const float*)d_in[2];
    const float* act_mask = (const float*)d_in[3];
    const float* spk_mean = (const float*)d_in[4];
    const float* act_mean = (const float*)d_in[5];
    const float* mix_logits = (const float*)d_in[6];
    float* out = (float*)d_out;

    weight_kernel<<<dim3(BB, 2), TT>>>(spk_mask, act_mask);
    sum_kernel<<<dim3(BB, 2, NSPLIT), 192>>>(spk_hist, act_hist);
    final_kernel<<<BB, DD>>>(spk_mean, act_mean, mix_logits, out);
}

// round 2
// speedup vs baseline: 1.9492x; 1.9492x over previous
#include <cuda_runtime.h>

#define BB 64
#define TT 512
#define DD 768
#define NSPLIT 2
#define MAXN 128
#define KMAX 115            // 0.1*0.9^115 ~ 5.4e-7; dropped tail -> ~5e-6 rel err
#define LOG2_DECAY (-0.15200309344504995f)  // log2(0.9)

// scratch (no allocations allowed)
__device__ int   g_ct[2 * BB * MAXN];   // compacted t indices
__device__ float g_cw[2 * BB * MAXN];   // compacted weights
__device__ int   g_cn[2 * BB];          // counts
__device__ float g_ne[2 * BB];          // nonempty flags
__device__ float g_part[2 * BB * NSPLIT * DD];

// One block per (b, stream): 512 threads, warp-ballot suffix counts + compaction.
__global__ void __launch_bounds__(TT) weight_kernel(const float* __restrict__ spk_mask,
                                                    const float* __restrict__ act_mask) {
    int b = blockIdx.x, s = blockIdx.y;
    int t = threadIdx.x, wid = t >> 5, lane = t & 31;
    const float* mask = (s == 0) ? spk_mask : act_mask;

    int m = (mask[b * TT + t] > 0.5f) ? 1 : 0;
    unsigned bal = __ballot_sync(0xFFFFFFFFu, m);

    __shared__ int wcnt[16];   // masked count per warp
    __shared__ int kcnt[16];   // kept count per warp
    if (lane == 0) wcnt[wid] = __popc(bal);
    __syncthreads();

    // masked count strictly after t
    int after = __popc(bal & (0xFFFFFFFEu << lane));
    int total = 0;
    #pragma unroll
    for (int i = 0; i < 16; i++) {
        int c = wcnt[i];
        total += c;
        if (i > wid) after += c;
    }
    int k = after;

    int keep = (m && k <= KMAX) ? 1 : 0;
    float w = keep ? 0.1f * exp2f((float)k * LOG2_DECAY) : 0.0f;

    unsigned kb = __ballot_sync(0xFFFFFFFFu, keep);
    if (lane == 0) kcnt[wid] = __popc(kb);
    __syncthreads();

    // deterministic rank = kept entries before t (ordered by t)
    int pos = __popc(kb & ((1u << lane) - 1u));
    int n = 0;
    #pragma unroll
    for (int i = 0; i < 16; i++) {
        int c = kcnt[i];
        if (i < wid) pos += c;
        n += c;
    }

    int sb = s * BB + b;
    if (keep) {
        g_ct[sb * MAXN + pos] = t;
        g_cw[sb * MAXN + pos] = w;
    }
    if (t == 0) {
        g_cn[sb] = n;
        g_ne[sb] = (total > 0) ? 1.0f : 0.0f;
    }
}

// grid (BB, 2, NSPLIT), 192 threads: each thread owns one float4 column of D.
__global__ void __launch_bounds__(192) sum_kernel(const float* __restrict__ spk,
                                                  const float* __restrict__ act) {
    int b = blockIdx.x, s = blockIdx.y, z = blockIdx.z;
    int sb = s * BB + b;
    int tid = threadIdx.x;
    const float* X = (s == 0) ? spk : act;

    __shared__ int   sidx[MAXN];
    __shared__ float swt[MAXN];
    int n = g_cn[sb];
    for (int j = tid; j < n; j += 192) {
        sidx[j] = g_ct[sb * MAXN + j];
        swt[j]  = g_cw[sb * MAXN + j];
    }
    __syncthreads();

    const float4* base = (const float4*)(X + (size_t)b * TT * DD) + tid;
    float4 acc = make_float4(0.f, 0.f, 0.f, 0.f);

    int j = z;
    // unroll-4: keep 4 independent LDG.128 in flight per thread
    for (; j + 3 * NSPLIT < n; j += 4 * NSPLIT) {
        int   t0 = sidx[j],              t1 = sidx[j + NSPLIT];
        int   t2 = sidx[j + 2 * NSPLIT], t3 = sidx[j + 3 * NSPLIT];
        float w0 = swt[j],               w1 = swt[j + NSPLIT];
        float w2 = swt[j + 2 * NSPLIT],  w3 = swt[j + 3 * NSPLIT];
        float4 v0 = base[(size_t)t0 * (DD / 4)];
        float4 v1 = base[(size_t)t1 * (DD / 4)];
        float4 v2 = base[(size_t)t2 * (DD / 4)];
        float4 v3 = base[(size_t)t3 * (DD / 4)];
        acc.x += w0 * v0.x; acc.y += w0 * v0.y; acc.z += w0 * v0.z; acc.w += w0 * v0.w;
        acc.x += w1 * v1.x; acc.y += w1 * v1.y; acc.z += w1 * v1.z; acc.w += w1 * v1.w;
        acc.x += w2 * v2.x; acc.y += w2 * v2.y; acc.z += w2 * v2.z; acc.w += w2 * v2.w;
        acc.x += w3 * v3.x; acc.y += w3 * v3.y; acc.z += w3 * v3.z; acc.w += w3 * v3.w;
    }
    for (; j < n; j += NSPLIT) {
        float w = swt[j];
        float4 v = base[(size_t)sidx[j] * (DD / 4)];
        acc.x += w * v.x; acc.y += w * v.y; acc.z += w * v.z; acc.w += w * v.w;
    }

    ((float4*)g_part)[(sb * NSPLIT + z) * (DD / 4) + tid] = acc;
}

__global__ void __launch_bounds__(DD) final_kernel(const float* __restrict__ spk_mean,
                                                   const float* __restrict__ act_mean,
                                                   const float* __restrict__ mix_logits,
                                                   float* __restrict__ out) {
    int b = blockIdx.x;
    int d = threadIdx.x;

    float l0 = mix_logits[0], l1 = mix_logits[1];
    float mx = fmaxf(l0, l1);
    float e0 = expf(l0 - mx), e1 = expf(l1 - mx);
    float inv = 1.0f / (e0 + e1);
    float w0 = e0 * inv, w1 = e1 * inv;

    const float* p0 = &g_part[(0 * BB + b) * NSPLIT * DD + d];
    float sum0 = 0.f;
    #pragma unroll
    for (int i = 0; i < NSPLIT; i++) sum0 += p0[i * DD];
    float cs = (g_ne[b] > 0.f) ? sum0 : spk_mean[b * DD + d];

    const float* p1 = &g_part[(1 * BB + b) * NSPLIT * DD + d];
    float sum1 = 0.f;
    #pragma unroll
    for (int i = 0; i < NSPLIT; i++) sum1 += p1[i * DD];
    float ca = (g_ne[BB + b] > 0.f) ? sum1 : act_mean[b * DD + d];

    out[b * DD + d] = w0 * cs + w1 * ca;                 // c
    out[BB * DD + b * DD + d] = cs;                      // c_spk
    out[2 * BB * DD + b * DD + d] = ca;                  // c_act
    if (b == 0 && d < 2) out[3 * BB * DD + d] = (d == 0) ? w0 : w1;  // w
}

extern "C" void kernel_launch(void* const* d_in, const int* in_sizes, int n_in,
                              void* d_out, int out_size) {
    const float* spk_hist  = (const float*)d_in[0];
    const float* spk_mask  = (const float*)d_in[1];
    const float* act_hist  = (const float*)d_in[2];
    const float* act_mask  = (const float*)d_in[3];
    const float* spk_mean  = (const float*)d_in[4];
    const float* act_mean  = (const float*)d_in[5];
    const float* mix_logits = (const float*)d_in[6];
    float* out = (float*)d_out;

    weight_kernel<<<dim3(BB, 2), TT>>>(spk_mask, act_mask);
    sum_kernel<<<dim3(BB, 2, NSPLIT), 192>>>(spk_hist, act_hist);
    final_kernel<<<BB, DD>>>(spk_mean, act_mean, mix_logits, out);
}

// round 3
// speedup vs baseline: 1.9870x; 1.0194x over previous
#include <cuda_runtime.h>

#define BB 64
#define TT 512
#define DD 768
#define MAXN 128
#define KMAX 115            // 0.1*0.9^115 ~ 5.4e-7 -> ~5e-6 rel err from dropped tail
#define LOG2_DECAY (-0.15200309344504995f)  // log2(0.9)

// cross-block handshake flags (zero-init; consumer resets after use -> replay-safe)
__device__ int g_flag[BB];

// Grid (BB, 2), 768 threads. One block per (batch, stream).
// Phase 1: ballot-scan mask -> compacted (t, w) list in smem.
// Phase 2: weighted sum over ~116 rows, one float column per thread.
// Phase 3: s=0 publishes c_spk; s=1 consumes it and writes c (+ w).
__global__ void __launch_bounds__(DD) fused_kernel(
    const float* __restrict__ spk_hist, const float* __restrict__ spk_mask,
    const float* __restrict__ act_hist, const float* __restrict__ act_mask,
    const float* __restrict__ spk_mean, const float* __restrict__ act_mean,
    const float* __restrict__ mix_logits, float* __restrict__ out)
{
    const int b = blockIdx.x, s = blockIdx.y;
    const int tid = threadIdx.x;
    const int wid = tid >> 5, lane = tid & 31;

    const float* mask = (s == 0) ? spk_mask : act_mask;
    const float* X    = (s == 0) ? spk_hist : act_hist;
    const float* mean = (s == 0) ? spk_mean : act_mean;

    __shared__ int   sidx[MAXN];
    __shared__ float swt[MAXN];
    __shared__ int   wcnt[16];   // masked count per warp (warps 0..15 cover T=512)
    __shared__ int   kcnt[16];   // kept count per warp

    // ---- Phase 1: weights via ballot suffix-scan (all warps execute all syncs) ----
    int m = 0;
    if (tid < TT) m = (mask[b * TT + tid] > 0.5f) ? 1 : 0;
    unsigned bal = __ballot_sync(0xFFFFFFFFu, m);
    if (lane == 0 && wid < 16) wcnt[wid] = __popc(bal);
    __syncthreads();

    int after = __popc(bal & (0xFFFFFFFEu << lane));  // masked strictly after t, same warp
    int total = 0;
    #pragma unroll
    for (int i = 0; i < 16; i++) {
        int c = wcnt[i];
        total += c;
        if (i > wid) after += c;
    }
    int k = after;
    int keep = (tid < TT && m && k <= KMAX) ? 1 : 0;
    float w = keep ? 0.1f * exp2f((float)k * LOG2_DECAY) : 0.0f;

    unsigned kb = __ballot_sync(0xFFFFFFFFu, keep);
    if (lane == 0 && wid < 16) kcnt[wid] = __popc(kb);
    __syncthreads();

    int pos = __popc(kb & ((1u << lane) - 1u));
    int n = 0;
    #pragma unroll
    for (int i = 0; i < 16; i++) {
        int c = kcnt[i];
        if (i < wid) pos += c;
        n += c;
    }
    if (keep) {
        sidx[pos] = tid;
        swt[pos]  = w;
    }
    __syncthreads();

    // ---- Phase 2: weighted sum; thread owns column d = tid ----
    const float* base = X + (size_t)b * TT * DD + tid;
    float acc = 0.0f;
    int j = 0;
    for (; j + 4 <= n; j += 4) {
        int   t0 = sidx[j],     t1 = sidx[j + 1], t2 = sidx[j + 2], t3 = sidx[j + 3];
        float w0 = swt[j],      w1 = swt[j + 1],  w2 = swt[j + 2],  w3 = swt[j + 3];
        float v0 = base[(size_t)t0 * DD];
        float v1 = base[(size_t)t1 * DD];
        float v2 = base[(size_t)t2 * DD];
        float v3 = base[(size_t)t3 * DD];
        acc += w0 * v0;
        acc += w1 * v1;
        acc += w2 * v2;
        acc += w3 * v3;
    }
    for (; j < n; j++) acc += swt[j] * base[(size_t)sidx[j] * DD];

    float cval = (total > 0) ? acc : mean[b * DD + tid];

    // softmax mix weights (cheap, both block types compute)
    float l0 = mix_logits[0], l1 = mix_logits[1];
    float mx = fmaxf(l0, l1);
    float e0 = expf(l0 - mx), e1 = expf(l1 - mx);
    float inv = 1.0f / (e0 + e1);
    float w0m = e0 * inv, w1m = e1 * inv;

    // ---- Phase 3 ----
    if (s == 0) {
        // producer: publish c_spk, then release flag
        out[BB * DD + b * DD + tid] = cval;
        __syncthreads();
        if (tid == 0) {
            __threadfence();
            atomicExch(&g_flag[b], 1);
        }
    } else {
        // consumer: write c_act, wait for peer, mix
        out[2 * BB * DD + b * DD + tid] = cval;
        if (tid == 0) {
            while (atomicAdd(&g_flag[b], 0) == 0) { }
            atomicExch(&g_flag[b], 0);   // reset for next graph replay
            __threadfence();
        }
        __syncthreads();
        float cspk = out[BB * DD + b * DD + tid];
        out[b * DD + tid] = w0m * cspk + w1m * cval;
        if (b == 0 && tid < 2) out[3 * BB * DD + tid] = (tid == 0) ? w0m : w1m;
    }
}

extern "C" void kernel_launch(void* const* d_in, const int* in_sizes, int n_in,
                              void* d_out, int out_size) {
    const float* spk_hist   = (const float*)d_in[0];
    const float* spk_mask   = (const float*)d_in[1];
    const float* act_hist   = (const float*)d_in[2];
    const float* act_mask   = (const float*)d_in[3];
    const float* spk_mean   = (const float*)d_in[4];
    const float* act_mean   = (const float*)d_in[5];
    const float* mix_logits = (const float*)d_in[6];
    float* out = (float*)d_out;

    fused_kernel<<<dim3(BB, 2), DD>>>(spk_hist, spk_mask, act_hist, act_mask,
                                      spk_mean, act_mean, mix_logits, out);
}

// round 4
// speedup vs baseline: 2.3058x; 1.1604x over previous
#include <cuda_runtime.h>

#define BB 64
#define TT 512
#define DD 768
#define MAXN 128
#define KMAX 115            // 0.1*0.9^115 ~ 5.4e-7 -> ~5e-6 rel err from dropped tail
#define LOG2_DECAY (-0.15200309344504995f)  // log2(0.9)
#define NC (DD / 4)         // 192 float4 columns

// cross-block handshake flags (zero-init; consumer resets after use -> replay-safe)
__device__ int g_flag[BB];

__device__ __forceinline__ void fma4(float4& a, float w, const float4& v) {
    a.x += w * v.x; a.y += w * v.y; a.z += w * v.z; a.w += w * v.w;
}

// Grid (BB, 2), 768 threads. One block per (batch, stream).
__global__ void __launch_bounds__(DD) fused_kernel(
    const float* __restrict__ spk_hist, const float* __restrict__ spk_mask,
    const float* __restrict__ act_hist, const float* __restrict__ act_mask,
    const float* __restrict__ spk_mean, const float* __restrict__ act_mean,
    const float* __restrict__ mix_logits, float* __restrict__ out)
{
    const int b = blockIdx.x, s = blockIdx.y;
    const int tid = threadIdx.x;
    const int wid = tid >> 5, lane = tid & 31;

    const float* mask = (s == 0) ? spk_mask : act_mask;
    const float* X    = (s == 0) ? spk_hist : act_hist;
    const float* mean = (s == 0) ? spk_mean : act_mean;

    __shared__ int    sidx[MAXN];
    __shared__ float  swt[MAXN];
    __shared__ int    wcnt[16];
    __shared__ int    kcnt[16];
    __shared__ int    s_total;
    __shared__ float4 spart[DD];   // 12 KB: 4 groups x 192 cols

    // ---- Phase 1: weights via ballot suffix-scan ----
    int m = 0;
    if (tid < TT) m = (mask[b * TT + tid] > 0.5f) ? 1 : 0;
    unsigned bal = __ballot_sync(0xFFFFFFFFu, m);
    if (lane == 0 && wid < 16) wcnt[wid] = __popc(bal);
    __syncthreads();

    int after = __popc(bal & (0xFFFFFFFEu << lane));
    int total = 0;
    #pragma unroll
    for (int i = 0; i < 16; i++) {
        int c = wcnt[i];
        total += c;
        if (i > wid) after += c;
    }
    int k = after;
    int keep = (tid < TT && m && k <= KMAX) ? 1 : 0;
    float w = keep ? 0.1f * exp2f((float)k * LOG2_DECAY) : 0.0f;

    unsigned kb = __ballot_sync(0xFFFFFFFFu, keep);
    if (lane == 0 && wid < 16) kcnt[wid] = __popc(kb);
    __syncthreads();

    int pos = __popc(kb & ((1u << lane) - 1u));
    int n = 0;
    #pragma unroll
    for (int i = 0; i < 16; i++) {
        int c = kcnt[i];
        if (i < wid) pos += c;
        n += c;
    }
    if (keep) {
        sidx[pos] = tid;
        swt[pos]  = w;
    }
    if (tid == 0) s_total = total;
    __syncthreads();

    // ---- Phase 2: weighted sum. Thread = (group g, float4 column c). ----
    const int g = tid / NC;       // 0..3: which slice of the t-list
    const int c = tid % NC;       // float4 column
    const float4* base = (const float4*)(X + (size_t)b * TT * DD) + c;

    float4 acc = make_float4(0.f, 0.f, 0.f, 0.f);
    int j = g;
    // 4 independent LDG.128 in flight per thread
    for (; j + 12 < n; j += 16) {
        int   t0 = sidx[j],      t1 = sidx[j + 4];
        int   t2 = sidx[j + 8],  t3 = sidx[j + 12];
        float w0 = swt[j],       w1 = swt[j + 4];
        float w2 = swt[j + 8],   w3 = swt[j + 12];
        float4 v0 = base[(size_t)t0 * NC];
        float4 v1 = base[(size_t)t1 * NC];
        float4 v2 = base[(size_t)t2 * NC];
        float4 v3 = base[(size_t)t3 * NC];
        fma4(acc, w0, v0);
        fma4(acc, w1, v1);
        fma4(acc, w2, v2);
        fma4(acc, w3, v3);
    }
    for (; j < n; j += 4) {
        float4 v = base[(size_t)sidx[j] * NC];
        fma4(acc, swt[j], v);
    }
    spart[g * NC + c] = acc;
    __syncthreads();

    // softmax mix weights
    float l0 = mix_logits[0], l1 = mix_logits[1];
    float mx = fmaxf(l0, l1);
    float e0 = expf(l0 - mx), e1 = expf(l1 - mx);
    float inv = 1.0f / (e0 + e1);
    float w0m = e0 * inv, w1m = e1 * inv;

    // ---- Phase 3: reduce groups, fallback, publish/consume ----
    float4 cval;
    if (tid < NC) {
        float4 a0 = spart[tid], a1 = spart[NC + tid];
        float4 a2 = spart[2 * NC + tid], a3 = spart[3 * NC + tid];
        cval = make_float4(a0.x + a1.x + a2.x + a3.x,
                           a0.y + a1.y + a2.y + a3.y,
                           a0.z + a1.z + a2.z + a3.z,
                           a0.w + a1.w + a2.w + a3.w);
        if (s_total == 0)
            cval = ((const float4*)(mean + (size_t)b * DD))[tid];
    }

    if (s == 0) {
        if (tid < NC)
            ((float4*)(out + (size_t)(BB + b) * DD))[tid] = cval;  // c_spk
        __syncthreads();
        if (tid == 0) {
            __threadfence();
            atomicExch(&g_flag[b], 1);
        }
    } else {
        if (tid < NC)
            ((float4*)(out + (size_t)(2 * BB + b) * DD))[tid] = cval;  // c_act
        if (tid == 0) {
            while (atomicAdd(&g_flag[b], 0) == 0) { }
            atomicExch(&g_flag[b], 0);   // reset for next graph replay
            __threadfence();
        }
        __syncthreads();
        if (tid < NC) {
            float4 cs = ((const float4*)(out + (size_t)(BB + b) * DD))[tid];
            float4 cm = make_float4(w0m * cs.x + w1m * cval.x,
                                    w0m * cs.y + w1m * cval.y,
                                    w0m * cs.z + w1m * cval.z,
                                    w0m * cs.w + w1m * cval.w);
            ((float4*)(out + (size_t)b * DD))[tid] = cm;   // c
        }
        if (b == 0 && tid < 2) out[3 * BB * DD + tid] = (tid == 0) ? w0m : w1m;  // w
    }
}

extern "C" void kernel_launch(void* const* d_in, const int* in_sizes, int n_in,
                              void* d_out, int out_size) {
    const float* spk_hist   = (const float*)d_in[0];
    const float* spk_mask   = (const float*)d_in[1];
    const float* act_hist   = (const float*)d_in[2];
    const float* act_mask   = (const float*)d_in[3];
    const float* spk_mean   = (const float*)d_in[4];
    const float* act_mean   = (const float*)d_in[5];
    const float* mix_logits = (const float*)d_in[6];
    float* out = (float*)d_out;

    fused_kernel<<<dim3(BB, 2), DD>>>(spk_hist, spk_mask, act_hist, act_mask,
                                      spk_mean, act_mean, mix_logits, out);
}

// round 5
// speedup vs baseline: 2.6744x; 1.1599x over previous
#include <cuda_runtime.h>

#define BB 64
#define TT 512
#define DD 768
#define MAXN 128
#define KMAX 87             // rel_err = 0.9^(KMAX+1) ~ 9.5e-5 (10x under 1e-3)
#define LOG2_DECAY (-0.15200309344504995f)  // log2(0.9)
#define NC (DD / 4)         // 192 float4 columns

// cross-block handshake flags (zero-init; consumer resets after use -> replay-safe)
__device__ int g_flag[BB];

__device__ __forceinline__ void fma4(float4& a, float w, const float4& v) {
    a.x += w * v.x; a.y += w * v.y; a.z += w * v.z; a.w += w * v.w;
}

// Grid (BB, 2), 768 threads. One block per (batch, stream).
__global__ void __launch_bounds__(DD, 1) fused_kernel(
    const float* __restrict__ spk_hist, const float* __restrict__ spk_mask,
    const float* __restrict__ act_hist, const float* __restrict__ act_mask,
    const float* __restrict__ spk_mean, const float* __restrict__ act_mean,
    const float* __restrict__ mix_logits, float* __restrict__ out)
{
    const int b = blockIdx.x, s = blockIdx.y;
    const int tid = threadIdx.x;
    const int wid = tid >> 5, lane = tid & 31;

    const float* mask = (s == 0) ? spk_mask : act_mask;
    const float* X    = (s == 0) ? spk_hist : act_hist;
    const float* mean = (s == 0) ? spk_mean : act_mean;

    __shared__ int    sidx[MAXN];
    __shared__ float  swt[MAXN];
    __shared__ int    wcnt[16];
    __shared__ int    kcnt[16];
    __shared__ int    s_total;
    __shared__ float4 spart[DD];   // 12 KB: 4 groups x 192 cols

    // ---- Phase 1: weights via ballot suffix-scan ----
    int m = 0;
    if (tid < TT) m = (mask[b * TT + tid] > 0.5f) ? 1 : 0;
    unsigned bal = __ballot_sync(0xFFFFFFFFu, m);
    if (lane == 0 && wid < 16) wcnt[wid] = __popc(bal);
    __syncthreads();

    int after = __popc(bal & (0xFFFFFFFEu << lane));
    int total = 0;
    #pragma unroll
    for (int i = 0; i < 16; i++) {
        int c = wcnt[i];
        total += c;
        if (i > wid) after += c;
    }
    int k = after;
    int keep = (tid < TT && m && k <= KMAX) ? 1 : 0;
    float w = keep ? 0.1f * exp2f((float)k * LOG2_DECAY) : 0.0f;

    unsigned kb = __ballot_sync(0xFFFFFFFFu, keep);
    if (lane == 0 && wid < 16) kcnt[wid] = __popc(kb);
    __syncthreads();

    int pos = __popc(kb & ((1u << lane) - 1u));
    int n = 0;
    #pragma unroll
    for (int i = 0; i < 16; i++) {
        int c = kcnt[i];
        if (i < wid) pos += c;
        n += c;
    }
    if (keep) {
        sidx[pos] = tid;
        swt[pos]  = w;
    }
    if (tid == 0) s_total = total;
    __syncthreads();

    // ---- Phase 2: weighted sum. Thread = (group g, float4 column c). ----
    const int g = tid / NC;       // 0..3: slice of the t-list (stride 4)
    const int c = tid % NC;       // float4 column
    const float4* base = (const float4*)(X + (size_t)b * TT * DD) + c;

    float4 acc = make_float4(0.f, 0.f, 0.f, 0.f);
    int j = g;
    // 8 independent LDG.128 in flight per thread
    for (; j + 28 < n; j += 32) {
        int t0 = sidx[j],      t1 = sidx[j + 4],  t2 = sidx[j + 8],  t3 = sidx[j + 12];
        int t4 = sidx[j + 16], t5 = sidx[j + 20], t6 = sidx[j + 24], t7 = sidx[j + 28];
        float w0 = swt[j],      w1 = swt[j + 4],  w2 = swt[j + 8],  w3 = swt[j + 12];
        float w4 = swt[j + 16], w5 = swt[j + 20], w6 = swt[j + 24], w7 = swt[j + 28];
        float4 v0 = base[(size_t)t0 * NC];
        float4 v1 = base[(size_t)t1 * NC];
        float4 v2 = base[(size_t)t2 * NC];
        float4 v3 = base[(size_t)t3 * NC];
        float4 v4 = base[(size_t)t4 * NC];
        float4 v5 = base[(size_t)t5 * NC];
        float4 v6 = base[(size_t)t6 * NC];
        float4 v7 = base[(size_t)t7 * NC];
        fma4(acc, w0, v0); fma4(acc, w1, v1); fma4(acc, w2, v2); fma4(acc, w3, v3);
        fma4(acc, w4, v4); fma4(acc, w5, v5); fma4(acc, w6, v6); fma4(acc, w7, v7);
    }
    // 4-wide tail
    for (; j + 12 < n; j += 16) {
        int   t0 = sidx[j],     t1 = sidx[j + 4], t2 = sidx[j + 8], t3 = sidx[j + 12];
        float w0 = swt[j],      w1 = swt[j + 4],  w2 = swt[j + 8],  w3 = swt[j + 12];
        float4 v0 = base[(size_t)t0 * NC];
        float4 v1 = base[(size_t)t1 * NC];
        float4 v2 = base[(size_t)t2 * NC];
        float4 v3 = base[(size_t)t3 * NC];
        fma4(acc, w0, v0); fma4(acc, w1, v1); fma4(acc, w2, v2); fma4(acc, w3, v3);
    }
    for (; j < n; j += 4) {
        float4 v = base[(size_t)sidx[j] * NC];
        fma4(acc, swt[j], v);
    }
    spart[g * NC + c] = acc;
    __syncthreads();

    // softmax mix weights
    float l0 = mix_logits[0], l1 = mix_logits[1];
    float mx = fmaxf(l0, l1);
    float e0 = expf(l0 - mx), e1 = expf(l1 - mx);
    float inv = 1.0f / (e0 + e1);
    float w0m = e0 * inv, w1m = e1 * inv;

    // ---- Phase 3: reduce groups, fallback, publish/consume ----
    float4 cval;
    if (tid < NC) {
        float4 a0 = spart[tid], a1 = spart[NC + tid];
        float4 a2 = spart[2 * NC + tid], a3 = spart[3 * NC + tid];
        cval = make_float4(a0.x + a1.x + a2.x + a3.x,
                           a0.y + a1.y + a2.y + a3.y,
                           a0.z + a1.z + a2.z + a3.z,
                           a0.w + a1.w + a2.w + a3.w);
        if (s_total == 0)
            cval = ((const float4*)(mean + (size_t)b * DD))[tid];
    }

    if (s == 0) {
        if (tid < NC)
            ((float4*)(out + (size_t)(BB + b) * DD))[tid] = cval;  // c_spk
        __syncthreads();
        if (tid == 0) {
            __threadfence();
            atomicExch(&g_flag[b], 1);
        }
    } else {
        if (tid < NC)
            ((float4*)(out + (size_t)(2 * BB + b) * DD))[tid] = cval;  // c_act
        if (tid == 0) {
            while (atomicAdd(&g_flag[b], 0) == 0) { }
            atomicExch(&g_flag[b], 0);   // reset for next graph replay
            __threadfence();
        }
        __syncthreads();
        if (tid < NC) {
            float4 cs = ((const float4*)(out + (size_t)(BB + b) * DD))[tid];
            float4 cm = make_float4(w0m * cs.x + w1m * cval.x,
                                    w0m * cs.y + w1m * cval.y,
                                    w0m * cs.z + w1m * cval.z,
                                    w0m * cs.w + w1m * cval.w);
            ((float4*)(out + (size_t)b * DD))[tid] = cm;   // c
        }
        if (b == 0 && tid < 2) out[3 * BB * DD + tid] = (tid == 0) ? w0m : w1m;  // w
    }
}

extern "C" void kernel_launch(void* const* d_in, const int* in_sizes, int n_in,
                              void* d_out, int out_size) {
    const float* spk_hist   = (const float*)d_in[0];
    const float* spk_mask   = (const float*)d_in[1];
    const float* act_hist   = (const float*)d_in[2];
    const float* act_mask   = (const float*)d_in[3];
    const float* spk_mean   = (const float*)d_in[4];
    const float* act_mean   = (const float*)d_in[5];
    const float* mix_logits = (const float*)d_in[6];
    float* out = (float*)d_out;

    fused_kernel<<<dim3(BB, 2), DD>>>(spk_hist, spk_mask, act_hist, act_mask,
                                      spk_mean, act_mean, mix_logits, out);
}